// round 9
// baseline (speedup 1.0000x reference)
#include <cuda_runtime.h>
#include <math.h>

#define BB 32
#define NN 1000
#define BN (BB*NN)
#define DD 64
#define HID 256
#define OBS 147
#define KSEL 500
#define NEGV (-1e8f)
#define NIT 16          // i-tiles of 64
#define NJC 4           // j-chunks of 256

// ---------------- scratch (device globals; no allocation) ----------------
__device__ float g_x[(size_t)BN*15];
__device__ float g_h4[(size_t)BB*256*64*4];       // [b][j>>2][d][j&3]
__device__ float g_hs[BN];
__device__ float g_hd[BN];
__device__ float g_comp[(size_t)BN*DD];
__device__ float g_coop[(size_t)BN*DD];
__device__ float g_pacc[(size_t)BB*NIT*NJC*4096];
__device__ float g_spart[(size_t)BB*NIT*NJC*64];
__device__ float g_xp[(size_t)BN*HID];
__device__ float g_scores[2*BN];
__device__ float g_w[2*BN];
__device__ float g_pp[2*BB*4*2*HID];
__device__ int   g_flag4;

// ---------------- f32x2 helpers ----------------
__device__ __forceinline__ unsigned long long pk2(float a, float b) {
    unsigned long long r;
    asm("mov.b64 %0, {%1,%2};" : "=l"(r) : "f"(a), "f"(b));
    return r;
}
__device__ __forceinline__ void upk2(unsigned long long v, float& a, float& b) {
    asm("mov.b64 {%0,%1}, %2;" : "=f"(a), "=f"(b) : "l"(v));
}
__device__ __forceinline__ unsigned long long ffma2(unsigned long long a, unsigned long long b,
                                                    unsigned long long c) {
    unsigned long long d;
    asm("fma.rn.f32x2 %0, %1, %2, %3;" : "=l"(d) : "l"(a), "l"(b), "l"(c));
    return d;
}

// ---------------- bool-width detection ----------------
__global__ void detect_kernel(const unsigned char* p, int nbytes) {
    __shared__ int any;
    if (threadIdx.x == 0) any = 0;
    __syncthreads();
    int loc = 0;
    for (int i = threadIdx.x; i < nbytes; i += blockDim.x)
        if ((i & 3) && p[i]) loc = 1;
    if (loc) any = 1;
    __syncthreads();
    if (threadIdx.x == 0) g_flag4 = any ? 0 : 1;
}

__device__ __forceinline__ bool bget(const void* p, size_t idx, int f4) {
    return f4 ? (((const int*)p)[idx] != 0) : (((const unsigned char*)p)[idx] != 0);
}

// ---------------- x = [cs(4), tp(2), vf(9)] ----------------
__global__ void buildx_kernel(const int* __restrict__ op_idx, const float* __restrict__ vf,
                              const float* __restrict__ cs_tab, const float* __restrict__ tp_tab) {
    int idx = blockIdx.x * blockDim.x + threadIdx.x;
    if (idx >= BN) return;
    int n = idx % NN;
    float* xr = g_x + (size_t)idx * 15;
    int op = op_idx[idx];
#pragma unroll
    for (int c = 0; c < 4; c++) xr[c] = cs_tab[n * 4 + c];
    xr[4] = tp_tab[op * 2 + 0];
    xr[5] = tp_tab[op * 2 + 1];
#pragma unroll
    for (int c = 0; c < 9; c++) xr[6 + c] = vf[(size_t)idx * 9 + c];
}

// ---------------- h = x @ W (quad-packed out), hd, hs ----------------
__global__ __launch_bounds__(256) void h_kernel(const float* __restrict__ xa, int Fa,
                                                const float* __restrict__ xb, int Fb,
                                                const float* __restrict__ W,
                                                const float* __restrict__ asrc,
                                                const float* __restrict__ adst) {
    __shared__ float xs[4][80];
    __shared__ float red[4][2][2];
    int nl = threadIdx.x >> 6, d = threadIdx.x & 63;
    size_t gn = (size_t)blockIdx.x * 4 + nl;
    for (int f = d; f < Fa; f += 64) xs[nl][f] = xa[gn * Fa + f];
    for (int f = d; f < Fb; f += 64) xs[nl][Fa + f] = xb[gn * Fb + f];
    __syncthreads();
    int F = Fa + Fb;
    float acc = 0.f;
    for (int f = 0; f < F; f++) acc = fmaf(xs[nl][f], W[f * DD + d], acc);
    int b = (int)(gn / NN), j = (int)(gn - (size_t)b * NN);
    g_h4[(((size_t)b * 256 + (j >> 2)) * 64 + d) * 4 + (j & 3)] = acc;
    float p1 = acc * adst[d], p2 = acc * asrc[d];
    for (int o = 16; o; o >>= 1) {
        p1 += __shfl_xor_sync(0xffffffffu, p1, o);
        p2 += __shfl_xor_sync(0xffffffffu, p2, o);
    }
    if ((d & 31) == 0) { red[nl][d >> 5][0] = p1; red[nl][d >> 5][1] = p2; }
    __syncthreads();
    if (threadIdx.x < 4) {
        size_t g2 = (size_t)blockIdx.x * 4 + threadIdx.x;
        g_hd[g2] = red[threadIdx.x][0][0] + red[threadIdx.x][1][0];
        g_hs[g2] = red[threadIdx.x][0][1] + red[threadIdx.x][1][1];
    }
}

// ---------------- fused GAT partial: (b, i-tile 64, j-chunk 256) ----------------
// Software pipeline: 8 subtiles of 32 j, double-buffered p4/h2, ONE sync per subtile.
// p-phase: thread = (one i, 8 consecutive j); lanes consecutive in i -> coalesced adj/dist.
// MMA: warp = 8 dst, lane = dims (lane, lane+32); LDS.128 h + LDS.128 p broadcast.
__global__ __launch_bounds__(256, 3) void gat_kernel(const float* __restrict__ wdp,
                                                     const void* __restrict__ adj,
                                                     const float* __restrict__ dist) {
    const float wd = *wdp;
    const int f4 = g_flag4;
    const int it = blockIdx.x, jc = blockIdx.y, b = blockIdx.z;
    const int iG0 = it * 64, jbase = jc * 256;
    const int t = threadIdx.x, w = t >> 5, lane = t & 31;
    const int pidx = (b * NJC + jc) * NIT + it;

    __shared__ ulonglong2 p4[2][64][9];             // [buf][i][j-quad], row 144B
    __shared__ ulonglong2 h2[2][8][64];             // [buf][q][d]
    __shared__ float hs_s[256];
    __shared__ float s_part[4][64];

    const int i_loc = t & 63;
    const int qq = t >> 6;                          // owns j = qq*8 .. qq*8+7 in subtile
    const int iG = iG0 + i_loc;
    const bool ivalid = iG < NN;
    const float hdv = ivalid ? g_hd[b * NN + iG] : 0.f;
    float sacc = 0.f;

    { int jG = jbase + t; hs_s[t] = (jG < NN) ? g_hs[b * NN + jG] : 0.f; }

    const unsigned char* ab = (const unsigned char*)adj;
    const int mult = f4 ? 4 : 1;
    const size_t abyte = (size_t)b * NN * NN * mult;

    unsigned long long acc[8][2];
#pragma unroll
    for (int g = 0; g < 8; g++) { acc[g][0] = 0ull; acc[g][1] = 0ull; }
    const int iw = w * 8;

    unsigned char av[8];
    float dv[8];
    float4 hr0, hr1;

#define LOADTILE(stv) do {                                                      \
    _Pragma("unroll")                                                           \
    for (int k = 0; k < 8; k++) {                                               \
        int jG = jbase + (stv) * 32 + qq * 8 + k;                               \
        bool ok = ivalid && (jG < NN);                                          \
        av[k] = ok ? ab[((size_t)jG * NN + iG) * mult + abyte] : 0;             \
        dv[k] = ok ? __ldg(&dist[(size_t)jG * NN + iG]) : 0.f;                  \
    }                                                                           \
} while (0)

    const float4* hbase4 = ((const float4*)g_h4) + (size_t)(b * 256 + jc * 64) * 64;
#define LOADH(stv) do {                                                         \
    const float4* hsrc = hbase4 + (size_t)(stv) * 512;                          \
    hr0 = __ldg(hsrc + t);                                                      \
    hr1 = __ldg(hsrc + t + 256);                                                \
} while (0)

    LOADTILE(0);
    LOADH(0);

    for (int st = 0; st < 8; st++) {
        const int buf = st & 1;
        // ---- STS h (prefetched regs) ----
        {
            float4* hdst = (float4*)&h2[buf][0][0];
            hdst[t] = hr0;
            hdst[t + 256] = hr1;
        }
        // ---- compute p from prefetched regs, STS as j-quads ----
        {
            float pv[8];
#pragma unroll
            for (int k = 0; k < 8; k++) {
                float p = 0.f;
                if (av[k]) {
                    float ev = hdv + hs_s[st * 32 + qq * 8 + k] + wd * dv[k];
                    ev = (ev >= 0.f) ? ev : 0.2f * ev;
                    p = __expf(ev);
                }
                sacc += p;
                pv[k] = p;
            }
            p4[buf][i_loc][qq * 2]     = make_ulonglong2(pk2(pv[0], pv[1]), pk2(pv[2], pv[3]));
            p4[buf][i_loc][qq * 2 + 1] = make_ulonglong2(pk2(pv[4], pv[5]), pk2(pv[6], pv[7]));
        }
        // ---- issue next subtile loads (consumed next iteration; overlap MMA) ----
        if (st < 7) { LOADTILE(st + 1); LOADH(st + 1); }
        __syncthreads();
        // ---- MMA on buf ----
#pragma unroll
        for (int q = 0; q < 8; q++) {
            ulonglong2 ha = h2[buf][q][lane];
            ulonglong2 hb = h2[buf][q][lane + 32];
#pragma unroll
            for (int g = 0; g < 8; g++) {
                ulonglong2 pq = p4[buf][iw + g][q];
                acc[g][0] = ffma2(pq.x, ha.x, acc[g][0]);
                acc[g][0] = ffma2(pq.y, ha.y, acc[g][0]);
                acc[g][1] = ffma2(pq.x, hb.x, acc[g][1]);
                acc[g][1] = ffma2(pq.y, hb.y, acc[g][1]);
            }
        }
    }
#undef LOADTILE
#undef LOADH

    // ---- reduce s per dst ----
    __syncthreads();
    s_part[qq][i_loc] = sacc;
    __syncthreads();
    if (t < 64)
        g_spart[(size_t)pidx * 64 + t] = s_part[0][t] + s_part[1][t] + s_part[2][t] + s_part[3][t];
    // ---- store partial acc ----
    float* pw = g_pacc + (size_t)pidx * 4096;
#pragma unroll
    for (int g = 0; g < 8; g++) {
        float a0, a1, b0, b1;
        upk2(acc[g][0], a0, a1);
        upk2(acc[g][1], b0, b1);
        int il = iw + g;
        pw[il * 64 + lane] = a0 + a1;
        pw[il * 64 + lane + 32] = b0 + b1;
    }
}

// ---------------- GAT finalize: reduce chunks, divide, elu ----------------
__global__ __launch_bounds__(256) void gat_fin_kernel(float* __restrict__ outrep) {
    int it = blockIdx.x, b = blockIdx.y;
    int t = threadIdx.x;
    __shared__ float s_tot[64];
    if (t < 64) {
        float s = 0.f;
#pragma unroll
        for (int jcc = 0; jcc < NJC; jcc++)
            s += g_spart[(size_t)((b * NJC + jcc) * NIT + it) * 64 + t];
        s_tot[t] = s;
    }
    __syncthreads();
#pragma unroll
    for (int e = 0; e < 16; e++) {
        int idx = t + e * 256;
        int il = idx >> 6, d = idx & 63;
        int ig = it * 64 + il;
        if (ig >= NN) continue;
        float a = 0.f;
#pragma unroll
        for (int jcc = 0; jcc < NJC; jcc++)
            a += g_pacc[(size_t)((b * NJC + jcc) * NIT + it) * 4096 + idx];
        float s = s_tot[il];
        float inv = (s > 0.f) ? 1.f / s : 0.f;
        float v = a * inv;
        v = (v > 0.f) ? v : expm1f(v);
        outrep[((size_t)b * NN + ig) * DD + d] = v;
    }
}

// ---------------- x_p = sag @ Wp + bp (32 nodes/block) ----------------
__global__ __launch_bounds__(256) void xp_kernel(const int* __restrict__ time_idx,
                                                 const int* __restrict__ op_idx,
                                                 const float* __restrict__ vf,
                                                 const float* __restrict__ time_tab,
                                                 const float* __restrict__ cs_tab,
                                                 const float* __restrict__ tp_tab,
                                                 const float* __restrict__ Wp,
                                                 const float* __restrict__ bp,
                                                 float* __restrict__ xp) {
    __shared__ __align__(16) float sag[OBS][32];
    int t = threadIdx.x, w = t >> 5, lane = t & 31;
    size_t gn0 = (size_t)blockIdx.x * 32;
#pragma unroll
    for (int nl2 = 0; nl2 < 4; nl2++) {
        int node = w * 4 + nl2;
        size_t gn = gn0 + node;
        int n = (int)(gn % NN);
        int ti = time_idx[gn], op = op_idx[gn];
        for (int f = lane; f < OBS; f += 32) {
            float v;
            if (f < 4)       v = time_tab[ti * 4 + f];
            else if (f < 8)  v = cs_tab[n * 4 + (f - 4)];
            else if (f < 10) v = tp_tab[op * 2 + (f - 8)];
            else if (f < 19) v = vf[gn * 9 + (f - 10)];
            else if (f < 83) v = g_comp[gn * 64 + (f - 19)];
            else             v = g_coop[gn * 64 + (f - 83)];
            sag[f][node] = v;
        }
    }
    __syncthreads();
    int h = t;
    float bv = bp[h];
    unsigned long long acc2[16];
    unsigned long long bv2 = pk2(bv, bv);
#pragma unroll
    for (int k = 0; k < 16; k++) acc2[k] = bv2;
#pragma unroll 3
    for (int f = 0; f < OBS; f++) {
        float wv = Wp[f * HID + h];
        unsigned long long wv2 = pk2(wv, wv);
        const ulonglong2* sp = (const ulonglong2*)&sag[f][0];
#pragma unroll
        for (int k2 = 0; k2 < 8; k2++) {
            ulonglong2 s2 = sp[k2];
            acc2[2 * k2]     = ffma2(wv2, s2.x, acc2[2 * k2]);
            acc2[2 * k2 + 1] = ffma2(wv2, s2.y, acc2[2 * k2 + 1]);
        }
    }
#pragma unroll
    for (int k = 0; k < 16; k++) {
        float x0, x1;
        upk2(acc2[k], x0, x1);
        xp[(gn0 + 2 * k) * HID + h] = x0;
        xp[(gn0 + 2 * k + 1) * HID + h] = x1;
    }
}

// ---------------- scores = xp . vpd / vpf ----------------
__global__ void scores_kernel(const float* __restrict__ xp, const float* __restrict__ vpd,
                              const float* __restrict__ vpf) {
    int w = threadIdx.x >> 5, lane = threadIdx.x & 31;
    size_t gn = (size_t)blockIdx.x * 8 + w;
    const float* r = xp + gn * HID;
    float sd = 0.f, sf = 0.f;
#pragma unroll
    for (int k = 0; k < 8; k++) {
        int hh = lane + 32 * k;
        float v = r[hh];
        sd = fmaf(v, vpd[hh], sd);
        sf = fmaf(v, vpf[hh], sf);
    }
    for (int o = 16; o; o >>= 1) {
        sd += __shfl_xor_sync(0xffffffffu, sd, o);
        sf += __shfl_xor_sync(0xffffffffu, sf, o);
    }
    if (lane == 0) { g_scores[gn] = sf; g_scores[BN + gn] = sd; }
}

// ---------------- pooling: weights (sort + softmax) ----------------
__global__ __launch_bounds__(256) void pool_w_kernel(const void* __restrict__ dpcs) {
    int b = blockIdx.x, type = blockIdx.y;
    __shared__ float sc[1024];
    __shared__ float sraw[NN];
    __shared__ float red[256];
    int f4 = g_flag4;
    const float* srow = g_scores + (size_t)type * BN + (size_t)b * NN;

    float lm = -INFINITY;
    for (int n = threadIdx.x; n < NN; n += 256) lm = fmaxf(lm, srow[n]);
    red[threadIdx.x] = lm;
    __syncthreads();
    for (int o = 128; o; o >>= 1) {
        if (threadIdx.x < o) red[threadIdx.x] = fmaxf(red[threadIdx.x], red[threadIdx.x + o]);
        __syncthreads();
    }
    float gm = red[0];
    __syncthreads();

    for (int n = threadIdx.x; n < 1024; n += 256) {
        float v = -INFINITY;
        if (n < NN) {
            bool mk = bget(dpcs, (size_t)b * NN + n, f4);
            bool valid = type ? mk : !mk;
            float sv = valid ? (srow[n] - gm) : NEGV;
            sraw[n] = sv;
            v = sv;
        }
        sc[n] = v;
    }
    __syncthreads();

    for (int k = 2; k <= 1024; k <<= 1)
        for (int j = k >> 1; j > 0; j >>= 1) {
            for (int i = threadIdx.x; i < 1024; i += 256) {
                int ixj = i ^ j;
                if (ixj > i) {
                    float a = sc[i], c = sc[ixj];
                    bool dirAsc = (i & k) == 0;
                    bool sw = dirAsc ? (a < c) : (a > c);
                    if (sw) { sc[i] = c; sc[ixj] = a; }
                }
            }
            __syncthreads();
        }
    float th = sc[KSEL - 1];
    float mx = sc[0];

    float part = 0.f;
    for (int n = threadIdx.x; n < NN; n += 256) {
        float sv = sraw[n];
        float p = (sv >= th) ? __expf(sv - mx) : 0.f;
        sraw[n] = p;
        part += p;
    }
    __syncthreads();
    red[threadIdx.x] = part;
    __syncthreads();
    for (int o = 128; o; o >>= 1) {
        if (threadIdx.x < o) red[threadIdx.x] += red[threadIdx.x + o];
        __syncthreads();
    }
    float invS = 1.f / red[0];
    float* wrow = g_w + (size_t)type * BN + (size_t)b * NN;
    for (int n = threadIdx.x; n < NN; n += 256) wrow[n] = sraw[n] * invS;
}

// ---------------- pooling: partial weighted sum/max ----------------
__global__ __launch_bounds__(256) void pool_sum_kernel(const float* __restrict__ xp) {
    int b = blockIdx.x, type = blockIdx.y, q = blockIdx.z;
    int h = threadIdx.x;
    const float* wrow = g_w + (size_t)type * BN + (size_t)b * NN;
    const float* xpb = xp + (size_t)b * NN * HID + h;
    int n0 = q * 250, n1 = n0 + 250;
    float sum = 0.f, mxv = -INFINITY;
    for (int n = n0; n < n1; n++) {
        float xv = wrow[n] * xpb[(size_t)n * HID];
        sum += xv;
        mxv = fmaxf(mxv, xv);
    }
    float* pp = g_pp + ((((size_t)type * BB + b) * 4 + q) * 2) * HID;
    pp[h] = sum;
    pp[HID + h] = mxv;
}

// ---------------- pooling: combine ----------------
__global__ void pool_fin_kernel(float* __restrict__ out) {
    int b = blockIdx.x, type = blockIdx.y;
    int h = threadIdx.x;
    float sum = 0.f, mxv = -INFINITY;
#pragma unroll
    for (int q = 0; q < 4; q++) {
        const float* pp = g_pp + ((((size_t)type * BB + b) * 4 + q) * 2) * HID;
        sum += pp[h];
        mxv = fmaxf(mxv, pp[HID + h]);
    }
    float* ob = out + (size_t)b * 1024 + type * 512;
    ob[h] = sum;
    ob[256 + h] = mxv;
}

// ---------------- launch ----------------
extern "C" void kernel_launch(void* const* d_in, const int* in_sizes, int n_in,
                              void* d_out, int out_size) {
    const int*   time_idx = (const int*)d_in[0];
    const int*   op_idx   = (const int*)d_in[1];
    const float* vf       = (const float*)d_in[2];
    const void*  dpcs     = d_in[3];
    const void*  adjc     = d_in[4];
    const void*  adjo     = d_in[5];
    const float* dist     = (const float*)d_in[6];
    const float* time_tab = (const float*)d_in[7];
    const float* tp_tab   = (const float*)d_in[8];
    const float* cs_tab   = (const float*)d_in[9];
    const float* Wc       = (const float*)d_in[10];
    const float* asrc_c   = (const float*)d_in[11];
    const float* adst_c   = (const float*)d_in[12];
    const float* wd_c     = (const float*)d_in[13];
    const float* Wco      = (const float*)d_in[14];
    const float* asrc_co  = (const float*)d_in[15];
    const float* adst_co  = (const float*)d_in[16];
    const float* wd_co    = (const float*)d_in[17];
    const float* Wp       = (const float*)d_in[18];
    const float* bp       = (const float*)d_in[19];
    const float* vpd      = (const float*)d_in[20];
    const float* vpf      = (const float*)d_in[21];
    float* out = (float*)d_out;

    float *px, *pcomp, *pcoop, *pxp;
    cudaGetSymbolAddress((void**)&px,    g_x);
    cudaGetSymbolAddress((void**)&pcomp, g_comp);
    cudaGetSymbolAddress((void**)&pcoop, g_coop);
    cudaGetSymbolAddress((void**)&pxp,   g_xp);

    detect_kernel<<<1, 256>>>((const unsigned char*)adjc, 32000);
    buildx_kernel<<<BN / 256 + 1, 256>>>(op_idx, vf, cs_tab, tp_tab);

    h_kernel<<<BN / 4, 256>>>(px, 15, (const float*)nullptr, 0, Wc, asrc_c, adst_c);
    gat_kernel<<<dim3(NIT, NJC, BB), 256>>>(wd_c, adjc, dist);
    gat_fin_kernel<<<dim3(NIT, BB), 256>>>(pcomp);

    h_kernel<<<BN / 4, 256>>>(px, 15, pcomp, 64, Wco, asrc_co, adst_co);
    gat_kernel<<<dim3(NIT, NJC, BB), 256>>>(wd_co, adjo, dist);
    gat_fin_kernel<<<dim3(NIT, BB), 256>>>(pcoop);

    xp_kernel<<<BN / 32, 256>>>(time_idx, op_idx, vf, time_tab, cs_tab, tp_tab, Wp, bp, pxp);
    scores_kernel<<<BN / 8, 256>>>(pxp, vpd, vpf);
    pool_w_kernel<<<dim3(BB, 2), 256>>>(dpcs);
    pool_sum_kernel<<<dim3(BB, 2, 4), 256>>>(pxp);
    pool_fin_kernel<<<dim3(BB, 2), 256>>>(out);
}

// round 11
// speedup vs baseline: 1.0327x; 1.0327x over previous
#include <cuda_runtime.h>
#include <math.h>

#define BB 32
#define NN 1000
#define BN (BB*NN)
#define DD 64
#define HID 256
#define OBS 147
#define KSEL 500
#define NEGV (-1e8f)
#define NIT 16          // i-tiles of 64
#define NJC 4           // j-chunks of 256
#define NQ 8            // pool n-splits

// ---------------- scratch (device globals; no allocation) ----------------
__device__ float g_h4[(size_t)BB*256*64*4];       // [b][j>>2][d][j&3]
__device__ float g_hs[BN];
__device__ float g_hd[BN];
__device__ float g_comp[(size_t)BN*DD];
__device__ float g_coop[(size_t)BN*DD];
__device__ float g_pacc[(size_t)BB*NIT*NJC*4096];
__device__ float g_spart[(size_t)BB*NIT*NJC*64];
__device__ float g_xp[(size_t)BN*HID];
__device__ float g_scores[2*BN];
__device__ float g_w[2*BN];
__device__ float g_pp[2*BB*NQ*2*HID];
__device__ int   g_flag4;

// ---------------- f32x2 helpers ----------------
__device__ __forceinline__ unsigned long long pk2(float a, float b) {
    unsigned long long r;
    asm("mov.b64 %0, {%1,%2};" : "=l"(r) : "f"(a), "f"(b));
    return r;
}
__device__ __forceinline__ void upk2(unsigned long long v, float& a, float& b) {
    asm("mov.b64 {%0,%1}, %2;" : "=f"(a), "=f"(b) : "l"(v));
}
__device__ __forceinline__ unsigned long long ffma2(unsigned long long a, unsigned long long b,
                                                    unsigned long long c) {
    unsigned long long d;
    asm("fma.rn.f32x2 %0, %1, %2, %3;" : "=l"(d) : "l"(a), "l"(b), "l"(c));
    return d;
}

// ---------------- bool-width detection ----------------
__global__ void detect_kernel(const unsigned char* p, int nbytes) {
    __shared__ int any;
    if (threadIdx.x == 0) any = 0;
    __syncthreads();
    int loc = 0;
    for (int i = threadIdx.x; i < nbytes; i += blockDim.x)
        if ((i & 3) && p[i]) loc = 1;
    if (loc) any = 1;
    __syncthreads();
    if (threadIdx.x == 0) g_flag4 = any ? 0 : 1;
}

__device__ __forceinline__ bool bget(const void* p, size_t idx, int f4) {
    return f4 ? (((const int*)p)[idx] != 0) : (((const unsigned char*)p)[idx] != 0);
}

// ---------------- h = x @ W (quad-packed out), hd, hs; x built inline ----------------
__global__ __launch_bounds__(256) void h_kernel(const float* __restrict__ comp,  // null => base
                                                const int* __restrict__ op_idx,
                                                const float* __restrict__ vf,
                                                const float* __restrict__ cs_tab,
                                                const float* __restrict__ tp_tab,
                                                const float* __restrict__ W,
                                                const float* __restrict__ asrc,
                                                const float* __restrict__ adst) {
    __shared__ float xs[4][80];
    __shared__ float red[4][2][2];
    int nl = threadIdx.x >> 6, d = threadIdx.x & 63;
    size_t gn = (size_t)blockIdx.x * 4 + nl;
    {
        int n = (int)(gn % NN);
        if (d < 4)       xs[nl][d] = cs_tab[n * 4 + d];
        else if (d < 6)  xs[nl][d] = tp_tab[op_idx[gn] * 2 + (d - 4)];
        else if (d < 15) xs[nl][d] = vf[gn * 9 + (d - 6)];
        if (comp) xs[nl][15 + d] = comp[gn * 64 + d];
    }
    __syncthreads();
    const int F = comp ? 79 : 15;
    float acc = 0.f;
    for (int f = 0; f < F; f++) acc = fmaf(xs[nl][f], W[f * DD + d], acc);
    int b = (int)(gn / NN), j = (int)(gn - (size_t)b * NN);
    g_h4[(((size_t)b * 256 + (j >> 2)) * 64 + d) * 4 + (j & 3)] = acc;
    float p1 = acc * adst[d], p2 = acc * asrc[d];
    for (int o = 16; o; o >>= 1) {
        p1 += __shfl_xor_sync(0xffffffffu, p1, o);
        p2 += __shfl_xor_sync(0xffffffffu, p2, o);
    }
    if ((d & 31) == 0) { red[nl][d >> 5][0] = p1; red[nl][d >> 5][1] = p2; }
    __syncthreads();
    if (threadIdx.x < 4) {
        size_t g2 = (size_t)blockIdx.x * 4 + threadIdx.x;
        g_hd[g2] = red[threadIdx.x][0][0] + red[threadIdx.x][1][0];
        g_hs[g2] = red[threadIdx.x][0][1] + red[threadIdx.x][1][1];
    }
}

// ---------------- fused GAT partial: (b, i-tile 64, j-chunk 256) ----------------
// 8 subtiles of 32 j, double-buffered p4/h2, one sync per subtile.
// p-phase: thread = (one i, 8 consecutive j); fast path uses one base pointer
// with immediate k*NN offsets (no per-k address math or predicates).
__global__ __launch_bounds__(256, 3) void gat_kernel(const float* __restrict__ wdp,
                                                     const void* __restrict__ adj,
                                                     const float* __restrict__ dist) {
    const float wd = *wdp;
    const int f4 = g_flag4;
    const int it = blockIdx.x, jc = blockIdx.y, b = blockIdx.z;
    const int iG0 = it * 64, jbase = jc * 256;
    const int t = threadIdx.x, w = t >> 5, lane = t & 31;
    const int pidx = (b * NJC + jc) * NIT + it;

    __shared__ ulonglong2 p4[2][64][9];
    __shared__ ulonglong2 h2[2][8][64];
    __shared__ float hs_s[256];
    __shared__ float s_part[4][64];

    const int i_loc = t & 63;
    const int qq = t >> 6;
    const int iG = iG0 + i_loc;
    const bool ivalid = iG < NN;
    const float hdv = ivalid ? g_hd[b * NN + iG] : 0.f;
    float sacc = 0.f;

    { int jG = jbase + t; hs_s[t] = (jG < NN) ? g_hs[b * NN + jG] : 0.f; }

    const unsigned char* ab = (const unsigned char*)adj;
    const int* ai = (const int*)adj;
    const size_t bbase = (size_t)b * NN * NN;

    unsigned long long acc[8][2];
#pragma unroll
    for (int g = 0; g < 8; g++) { acc[g][0] = 0ull; acc[g][1] = 0ull; }
    const int iw = w * 8;

    unsigned char av[8];
    float dv[8];
    float4 hr0, hr1;

#define LOADTILE(stv) do {                                                      \
    int jG0 = jbase + (stv) * 32 + qq * 8;                                      \
    if (ivalid && (jG0 + 8 <= NN)) {                                            \
        const float* dp = dist + (size_t)jG0 * NN + iG;                         \
        if (!f4) {                                                              \
            const unsigned char* ap = ab + bbase + (size_t)jG0 * NN + iG;       \
            _Pragma("unroll")                                                   \
            for (int k = 0; k < 8; k++) {                                       \
                av[k] = __ldg(ap + k * NN);                                     \
                dv[k] = __ldg(dp + k * NN);                                     \
            }                                                                   \
        } else {                                                                \
            const int* ap = ai + bbase + (size_t)jG0 * NN + iG;                 \
            _Pragma("unroll")                                                   \
            for (int k = 0; k < 8; k++) {                                       \
                av[k] = (unsigned char)(__ldg(ap + k * NN) != 0);               \
                dv[k] = __ldg(dp + k * NN);                                     \
            }                                                                   \
        }                                                                       \
    } else {                                                                    \
        _Pragma("unroll")                                                       \
        for (int k = 0; k < 8; k++) {                                           \
            int jG = jG0 + k;                                                   \
            bool ok = ivalid && (jG < NN);                                      \
            av[k] = ok ? (f4 ? (unsigned char)(ai[bbase + (size_t)jG * NN + iG] != 0) \
                             : ab[bbase + (size_t)jG * NN + iG]) : 0;           \
            dv[k] = ok ? __ldg(&dist[(size_t)jG * NN + iG]) : 0.f;              \
        }                                                                       \
    }                                                                           \
} while (0)

    const float4* hbase4 = ((const float4*)g_h4) + (size_t)(b * 256 + jc * 64) * 64;
#define LOADH(stv) do {                                                         \
    const float4* hsrc = hbase4 + (size_t)(stv) * 512;                          \
    hr0 = __ldg(hsrc + t);                                                      \
    hr1 = __ldg(hsrc + t + 256);                                                \
} while (0)

    LOADTILE(0);
    LOADH(0);

    for (int st = 0; st < 8; st++) {
        const int buf = st & 1;
        {
            float4* hdst = (float4*)&h2[buf][0][0];
            hdst[t] = hr0;
            hdst[t + 256] = hr1;
        }
        {
            float pv[8];
#pragma unroll
            for (int k = 0; k < 8; k++) {
                float p = 0.f;
                if (av[k]) {
                    float ev = hdv + hs_s[st * 32 + qq * 8 + k] + wd * dv[k];
                    ev = fmaxf(ev, 0.2f * ev);   // leaky_relu(0.2)
                    p = __expf(ev);
                }
                sacc += p;
                pv[k] = p;
            }
            p4[buf][i_loc][qq * 2]     = make_ulonglong2(pk2(pv[0], pv[1]), pk2(pv[2], pv[3]));
            p4[buf][i_loc][qq * 2 + 1] = make_ulonglong2(pk2(pv[4], pv[5]), pk2(pv[6], pv[7]));
        }
        if (st < 7) { LOADTILE(st + 1); LOADH(st + 1); }
        __syncthreads();
#pragma unroll
        for (int q = 0; q < 8; q++) {
            ulonglong2 ha = h2[buf][q][lane];
            ulonglong2 hb = h2[buf][q][lane + 32];
#pragma unroll
            for (int g = 0; g < 8; g++) {
                ulonglong2 pq = p4[buf][iw + g][q];
                acc[g][0] = ffma2(pq.x, ha.x, acc[g][0]);
                acc[g][0] = ffma2(pq.y, ha.y, acc[g][0]);
                acc[g][1] = ffma2(pq.x, hb.x, acc[g][1]);
                acc[g][1] = ffma2(pq.y, hb.y, acc[g][1]);
            }
        }
    }
#undef LOADTILE
#undef LOADH

    __syncthreads();
    s_part[qq][i_loc] = sacc;
    __syncthreads();
    if (t < 64)
        g_spart[(size_t)pidx * 64 + t] = s_part[0][t] + s_part[1][t] + s_part[2][t] + s_part[3][t];
    float* pw = g_pacc + (size_t)pidx * 4096;
#pragma unroll
    for (int g = 0; g < 8; g++) {
        float a0, a1, b0, b1;
        upk2(acc[g][0], a0, a1);
        upk2(acc[g][1], b0, b1);
        int il = iw + g;
        pw[il * 64 + lane] = a0 + a1;
        pw[il * 64 + lane + 32] = b0 + b1;
    }
}

// ---------------- GAT finalize: reduce chunks, divide, elu ----------------
__global__ __launch_bounds__(256) void gat_fin_kernel(float* __restrict__ outrep) {
    int it = blockIdx.x, b = blockIdx.y;
    int t = threadIdx.x;
    __shared__ float s_tot[64];
    if (t < 64) {
        float s = 0.f;
#pragma unroll
        for (int jcc = 0; jcc < NJC; jcc++)
            s += g_spart[(size_t)((b * NJC + jcc) * NIT + it) * 64 + t];
        s_tot[t] = s;
    }
    __syncthreads();
#pragma unroll
    for (int e = 0; e < 16; e++) {
        int idx = t + e * 256;
        int il = idx >> 6, d = idx & 63;
        int ig = it * 64 + il;
        if (ig >= NN) continue;
        float a = 0.f;
#pragma unroll
        for (int jcc = 0; jcc < NJC; jcc++)
            a += g_pacc[(size_t)((b * NJC + jcc) * NIT + it) * 4096 + idx];
        float s = s_tot[il];
        float inv = (s > 0.f) ? 1.f / s : 0.f;
        float v = a * inv;
        v = (v > 0.f) ? v : expm1f(v);
        outrep[((size_t)b * NN + ig) * DD + d] = v;
    }
}

// ---------------- x_p = sag @ Wp + bp (32 nodes/block) ----------------
__global__ __launch_bounds__(256) void xp_kernel(const int* __restrict__ time_idx,
                                                 const int* __restrict__ op_idx,
                                                 const float* __restrict__ vf,
                                                 const float* __restrict__ time_tab,
                                                 const float* __restrict__ cs_tab,
                                                 const float* __restrict__ tp_tab,
                                                 const float* __restrict__ Wp,
                                                 const float* __restrict__ bp,
                                                 float* __restrict__ xp) {
    __shared__ __align__(16) float sag[OBS][32];
    int t = threadIdx.x, w = t >> 5, lane = t & 31;
    size_t gn0 = (size_t)blockIdx.x * 32;
#pragma unroll
    for (int nl2 = 0; nl2 < 4; nl2++) {
        int node = w * 4 + nl2;
        size_t gn = gn0 + node;
        int n = (int)(gn % NN);
        int ti = time_idx[gn], op = op_idx[gn];
        for (int f = lane; f < OBS; f += 32) {
            float v;
            if (f < 4)       v = time_tab[ti * 4 + f];
            else if (f < 8)  v = cs_tab[n * 4 + (f - 4)];
            else if (f < 10) v = tp_tab[op * 2 + (f - 8)];
            else if (f < 19) v = vf[gn * 9 + (f - 10)];
            else if (f < 83) v = g_comp[gn * 64 + (f - 19)];
            else             v = g_coop[gn * 64 + (f - 83)];
            sag[f][node] = v;
        }
    }
    __syncthreads();
    int h = t;
    float bv = bp[h];
    unsigned long long acc2[16];
    unsigned long long bv2 = pk2(bv, bv);
#pragma unroll
    for (int k = 0; k < 16; k++) acc2[k] = bv2;
#pragma unroll 3
    for (int f = 0; f < OBS; f++) {
        float wv = Wp[f * HID + h];
        unsigned long long wv2 = pk2(wv, wv);
        const ulonglong2* sp = (const ulonglong2*)&sag[f][0];
#pragma unroll
        for (int k2 = 0; k2 < 8; k2++) {
            ulonglong2 s2 = sp[k2];
            acc2[2 * k2]     = ffma2(wv2, s2.x, acc2[2 * k2]);
            acc2[2 * k2 + 1] = ffma2(wv2, s2.y, acc2[2 * k2 + 1]);
        }
    }
#pragma unroll
    for (int k = 0; k < 16; k++) {
        float x0, x1;
        upk2(acc2[k], x0, x1);
        xp[(gn0 + 2 * k) * HID + h] = x0;
        xp[(gn0 + 2 * k + 1) * HID + h] = x1;
    }
}

// ---------------- scores = xp . vpd / vpf ----------------
__global__ void scores_kernel(const float* __restrict__ xp, const float* __restrict__ vpd,
                              const float* __restrict__ vpf) {
    int w = threadIdx.x >> 5, lane = threadIdx.x & 31;
    size_t gn = (size_t)blockIdx.x * 8 + w;
    const float* r = xp + gn * HID;
    float sd = 0.f, sf = 0.f;
#pragma unroll
    for (int k = 0; k < 8; k++) {
        int hh = lane + 32 * k;
        float v = r[hh];
        sd = fmaf(v, vpd[hh], sd);
        sf = fmaf(v, vpf[hh], sf);
    }
    for (int o = 16; o; o >>= 1) {
        sd += __shfl_xor_sync(0xffffffffu, sd, o);
        sf += __shfl_xor_sync(0xffffffffu, sf, o);
    }
    if (lane == 0) { g_scores[gn] = sf; g_scores[BN + gn] = sd; }
}

// ---------------- pooling: weights (sort + softmax) ----------------
__global__ __launch_bounds__(256) void pool_w_kernel(const void* __restrict__ dpcs) {
    int b = blockIdx.x, type = blockIdx.y;
    __shared__ float sc[1024];
    __shared__ float sraw[NN];
    __shared__ float red[256];
    int f4 = g_flag4;
    const float* srow = g_scores + (size_t)type * BN + (size_t)b * NN;

    float lm = -INFINITY;
    for (int n = threadIdx.x; n < NN; n += 256) lm = fmaxf(lm, srow[n]);
    red[threadIdx.x] = lm;
    __syncthreads();
    for (int o = 128; o; o >>= 1) {
        if (threadIdx.x < o) red[threadIdx.x] = fmaxf(red[threadIdx.x], red[threadIdx.x + o]);
        __syncthreads();
    }
    float gm = red[0];
    __syncthreads();

    for (int n = threadIdx.x; n < 1024; n += 256) {
        float v = -INFINITY;
        if (n < NN) {
            bool mk = bget(dpcs, (size_t)b * NN + n, f4);
            bool valid = type ? mk : !mk;
            float sv = valid ? (srow[n] - gm) : NEGV;
            sraw[n] = sv;
            v = sv;
        }
        sc[n] = v;
    }
    __syncthreads();

    for (int k = 2; k <= 1024; k <<= 1)
        for (int j = k >> 1; j > 0; j >>= 1) {
            for (int i = threadIdx.x; i < 1024; i += 256) {
                int ixj = i ^ j;
                if (ixj > i) {
                    float a = sc[i], c = sc[ixj];
                    bool dirAsc = (i & k) == 0;
                    bool sw = dirAsc ? (a < c) : (a > c);
                    if (sw) { sc[i] = c; sc[ixj] = a; }
                }
            }
            __syncthreads();
        }
    float th = sc[KSEL - 1];
    float mx = sc[0];

    float part = 0.f;
    for (int n = threadIdx.x; n < NN; n += 256) {
        float sv = sraw[n];
        float p = (sv >= th) ? __expf(sv - mx) : 0.f;
        sraw[n] = p;
        part += p;
    }
    __syncthreads();
    red[threadIdx.x] = part;
    __syncthreads();
    for (int o = 128; o; o >>= 1) {
        if (threadIdx.x < o) red[threadIdx.x] += red[threadIdx.x + o];
        __syncthreads();
    }
    float invS = 1.f / red[0];
    float* wrow = g_w + (size_t)type * BN + (size_t)b * NN;
    for (int n = threadIdx.x; n < NN; n += 256) wrow[n] = sraw[n] * invS;
}

// ---------------- pooling: partial weighted sum/max ----------------
__global__ __launch_bounds__(256) void pool_sum_kernel(const float* __restrict__ xp) {
    int b = blockIdx.x, type = blockIdx.y, q = blockIdx.z;
    int h = threadIdx.x;
    const float* wrow = g_w + (size_t)type * BN + (size_t)b * NN;
    const float* xpb = xp + (size_t)b * NN * HID + h;
    int n0 = q * 125, n1 = n0 + 125;
    float sum = 0.f, mxv = -INFINITY;
#pragma unroll 5
    for (int n = n0; n < n1; n++) {
        float xv = __ldg(&wrow[n]) * __ldg(&xpb[(size_t)n * HID]);
        sum += xv;
        mxv = fmaxf(mxv, xv);
    }
    float* pp = g_pp + ((((size_t)type * BB + b) * NQ + q) * 2) * HID;
    pp[h] = sum;
    pp[HID + h] = mxv;
}

// ---------------- pooling: combine ----------------
__global__ void pool_fin_kernel(float* __restrict__ out) {
    int b = blockIdx.x, type = blockIdx.y;
    int h = threadIdx.x;
    float sum = 0.f, mxv = -INFINITY;
#pragma unroll
    for (int q = 0; q < NQ; q++) {
        const float* pp = g_pp + ((((size_t)type * BB + b) * NQ + q) * 2) * HID;
        sum += pp[h];
        mxv = fmaxf(mxv, pp[HID + h]);
    }
    float* ob = out + (size_t)b * 1024 + type * 512;
    ob[h] = sum;
    ob[256 + h] = mxv;
}

// ---------------- launch ----------------
extern "C" void kernel_launch(void* const* d_in, const int* in_sizes, int n_in,
                              void* d_out, int out_size) {
    const int*   time_idx = (const int*)d_in[0];
    const int*   op_idx   = (const int*)d_in[1];
    const float* vf       = (const float*)d_in[2];
    const void*  dpcs     = d_in[3];
    const void*  adjc     = d_in[4];
    const void*  adjo     = d_in[5];
    const float* dist     = (const float*)d_in[6];
    const float* time_tab = (const float*)d_in[7];
    const float* tp_tab   = (const float*)d_in[8];
    const float* cs_tab   = (const float*)d_in[9];
    const float* Wc       = (const float*)d_in[10];
    const float* asrc_c   = (const float*)d_in[11];
    const float* adst_c   = (const float*)d_in[12];
    const float* wd_c     = (const float*)d_in[13];
    const float* Wco      = (const float*)d_in[14];
    const float* asrc_co  = (const float*)d_in[15];
    const float* adst_co  = (const float*)d_in[16];
    const float* wd_co    = (const float*)d_in[17];
    const float* Wp       = (const float*)d_in[18];
    const float* bp       = (const float*)d_in[19];
    const float* vpd      = (const float*)d_in[20];
    const float* vpf      = (const float*)d_in[21];
    float* out = (float*)d_out;

    float *pcomp, *pcoop, *pxp;
    cudaGetSymbolAddress((void**)&pcomp, g_comp);
    cudaGetSymbolAddress((void**)&pcoop, g_coop);
    cudaGetSymbolAddress((void**)&pxp,   g_xp);

    detect_kernel<<<1, 256>>>((const unsigned char*)adjc, 32000);

    h_kernel<<<BN / 4, 256>>>((const float*)nullptr, op_idx, vf, cs_tab, tp_tab,
                              Wc, asrc_c, adst_c);
    gat_kernel<<<dim3(NIT, NJC, BB), 256>>>(wd_c, adjc, dist);
    gat_fin_kernel<<<dim3(NIT, BB), 256>>>(pcomp);

    h_kernel<<<BN / 4, 256>>>(pcomp, op_idx, vf, cs_tab, tp_tab,
                              Wco, asrc_co, adst_co);
    gat_kernel<<<dim3(NIT, NJC, BB), 256>>>(wd_co, adjo, dist);
    gat_fin_kernel<<<dim3(NIT, BB), 256>>>(pcoop);

    xp_kernel<<<BN / 32, 256>>>(time_idx, op_idx, vf, time_tab, cs_tab, tp_tab, Wp, bp, pxp);
    scores_kernel<<<BN / 8, 256>>>(pxp, vpd, vpf);
    pool_w_kernel<<<dim3(BB, 2), 256>>>(dpcs);
    pool_sum_kernel<<<dim3(BB, 2, NQ), 256>>>(pxp);
    pool_fin_kernel<<<dim3(BB, 2), 256>>>(out);
}

// round 14
// speedup vs baseline: 1.4169x; 1.3721x over previous
#include <cuda_runtime.h>
#include <cuda_bf16.h>
#include <math.h>
#include <stdint.h>

#define BB 32
#define NN 1000
#define BN (BB*NN)
#define DD 64
#define HID 256
#define OBS 147
#define KSEL 500
#define NEGV (-1e8f)
#define NIT 16          // i-tiles of 64
#define NJC 4           // j-chunks of 256
#define NQ 8            // pool n-splits

// ---------------- scratch (device globals; no allocation) ----------------
__device__ __nv_bfloat16 g_hrh[(size_t)BB*1024*64];  // h hi, row-major [b][j][d]
__device__ __nv_bfloat16 g_hrl[(size_t)BB*1024*64];  // h lo residual
__device__ float g_hs[BN];
__device__ float g_hd[BN];
__device__ float g_comp[(size_t)BN*DD];
__device__ float g_coop[(size_t)BN*DD];
__device__ float g_pacc[(size_t)BB*NIT*NJC*4096];
__device__ float g_spart[(size_t)BB*NIT*NJC*64];
__device__ float g_xp[(size_t)BN*HID];
__device__ float g_scores[2*BN];
__device__ float g_w[2*BN];
__device__ float g_pp[2*BB*NQ*2*HID];
__device__ int   g_flag4;

// ---------------- f32x2 helpers (xp) ----------------
__device__ __forceinline__ unsigned long long pk2(float a, float b) {
    unsigned long long r;
    asm("mov.b64 %0, {%1,%2};" : "=l"(r) : "f"(a), "f"(b));
    return r;
}
__device__ __forceinline__ void upk2(unsigned long long v, float& a, float& b) {
    asm("mov.b64 {%0,%1}, %2;" : "=f"(a), "=f"(b) : "l"(v));
}
__device__ __forceinline__ unsigned long long ffma2(unsigned long long a, unsigned long long b,
                                                    unsigned long long c) {
    unsigned long long d;
    asm("fma.rn.f32x2 %0, %1, %2, %3;" : "=l"(d) : "l"(a), "l"(b), "l"(c));
    return d;
}

// ---------------- mma / ldmatrix helpers ----------------
__device__ __forceinline__ uint32_t smem_to_u32(const void* p) {
    uint32_t a;
    asm("{ .reg .u64 tmp; cvta.to.shared.u64 tmp, %1; cvt.u32.u64 %0, tmp; }"
        : "=r"(a) : "l"(p));
    return a;
}
__device__ __forceinline__ void ldsm_x4(uint32_t* r, uint32_t addr) {
    asm volatile("ldmatrix.sync.aligned.m8n8.x4.shared.b16 {%0,%1,%2,%3}, [%4];"
                 : "=r"(r[0]), "=r"(r[1]), "=r"(r[2]), "=r"(r[3]) : "r"(addr));
}
__device__ __forceinline__ void ldsm_x4_t(uint32_t* r, uint32_t addr) {
    asm volatile("ldmatrix.sync.aligned.m8n8.x4.trans.shared.b16 {%0,%1,%2,%3}, [%4];"
                 : "=r"(r[0]), "=r"(r[1]), "=r"(r[2]), "=r"(r[3]) : "r"(addr));
}
__device__ __forceinline__ void mma_bf16(float* d, const uint32_t* a, uint32_t b0, uint32_t b1) {
    asm volatile("mma.sync.aligned.m16n8k16.row.col.f32.bf16.bf16.f32 "
                 "{%0,%1,%2,%3}, {%4,%5,%6,%7}, {%8,%9}, {%0,%1,%2,%3};"
                 : "+f"(d[0]), "+f"(d[1]), "+f"(d[2]), "+f"(d[3])
                 : "r"(a[0]), "r"(a[1]), "r"(a[2]), "r"(a[3]), "r"(b0), "r"(b1));
}
__device__ __forceinline__ uint32_t pkbf(__nv_bfloat16 a, __nv_bfloat16 b) {
    return (uint32_t)__bfloat16_as_ushort(a) | ((uint32_t)__bfloat16_as_ushort(b) << 16);
}

// ---------------- bool-width detection ----------------
__global__ void detect_kernel(const unsigned char* p, int nbytes) {
    __shared__ int any;
    if (threadIdx.x == 0) any = 0;
    __syncthreads();
    int loc = 0;
    for (int i = threadIdx.x; i < nbytes; i += blockDim.x)
        if ((i & 3) && p[i]) loc = 1;
    if (loc) any = 1;
    __syncthreads();
    if (threadIdx.x == 0) g_flag4 = any ? 0 : 1;
}
__device__ __forceinline__ bool bget(const void* p, size_t idx, int f4) {
    return f4 ? (((const int*)p)[idx] != 0) : (((const unsigned char*)p)[idx] != 0);
}

// ---------------- h = x @ W (bf16 hi/lo rows out), hd, hs; x built inline ----------------
__global__ __launch_bounds__(256) void h_kernel(const float* __restrict__ comp,
                                                const int* __restrict__ op_idx,
                                                const float* __restrict__ vf,
                                                const float* __restrict__ cs_tab,
                                                const float* __restrict__ tp_tab,
                                                const float* __restrict__ W,
                                                const float* __restrict__ asrc,
                                                const float* __restrict__ adst) {
    __shared__ float xs[4][80];
    __shared__ float red[4][2][2];
    int nl = threadIdx.x >> 6, d = threadIdx.x & 63;
    size_t gn = (size_t)blockIdx.x * 4 + nl;
    {
        int n = (int)(gn % NN);
        if (d < 4)       xs[nl][d] = cs_tab[n * 4 + d];
        else if (d < 6)  xs[nl][d] = tp_tab[op_idx[gn] * 2 + (d - 4)];
        else if (d < 15) xs[nl][d] = vf[gn * 9 + (d - 6)];
        if (comp) xs[nl][15 + d] = comp[gn * 64 + d];
    }
    __syncthreads();
    const int F = comp ? 79 : 15;
    float acc = 0.f;
    for (int f = 0; f < F; f++) acc = fmaf(xs[nl][f], W[f * DD + d], acc);
    int b = (int)(gn / NN), j = (int)(gn - (size_t)b * NN);
    __nv_bfloat16 hi = __float2bfloat16(acc);
    float res = acc - __bfloat162float(hi);
    size_t ro = ((size_t)b * 1024 + j) * 64 + d;
    g_hrh[ro] = hi;
    g_hrl[ro] = __float2bfloat16(res);
    float p1 = acc * adst[d], p2 = acc * asrc[d];
    for (int o = 16; o; o >>= 1) {
        p1 += __shfl_xor_sync(0xffffffffu, p1, o);
        p2 += __shfl_xor_sync(0xffffffffu, p2, o);
    }
    if ((d & 31) == 0) { red[nl][d >> 5][0] = p1; red[nl][d >> 5][1] = p2; }
    __syncthreads();
    if (threadIdx.x < 4) {
        size_t g2 = (size_t)blockIdx.x * 4 + threadIdx.x;
        g_hd[g2] = red[threadIdx.x][0][0] + red[threadIdx.x][1][0];
        g_hs[g2] = red[threadIdx.x][0][1] + red[threadIdx.x][1][1];
    }
}

// ---------------- tensor GAT partial: (b, i-tile 64, j-chunk 256) ----------------
// Per 64-j subtile: p-phase (R11 coalesced loads) writes p bf16 hi/lo [64i][64j],
// h tiles copied bf16 hi/lo [64j][64d]; then warp-level mma.m16n8k16 (3-term).
// smem rows padded to 144B (16B-aligned, LDSM conflict-free).
#define PROW 144
__global__ __launch_bounds__(256) void gat_kernel(const float* __restrict__ wdp,
                                                  const void* __restrict__ adj,
                                                  const float* __restrict__ dist) {
    __shared__ __align__(16) char smPH[64 * PROW];
    __shared__ __align__(16) char smPL[64 * PROW];
    __shared__ __align__(16) char smHH[64 * PROW];
    __shared__ __align__(16) char smHL[64 * PROW];
    __shared__ float hs_s[256];
    __shared__ float s_part[4][64];

    const float wd = *wdp;
    const int f4 = g_flag4;
    const int it = blockIdx.x, jc = blockIdx.y, b = blockIdx.z;
    const int iG0 = it * 64, jbase = jc * 256;
    const int t = threadIdx.x, w = t >> 5, lane = t & 31;
    const int pidx = (b * NJC + jc) * NIT + it;
    const int wi = w & 3, wdg = w >> 2;

    const int i_loc = t & 63;
    const int qq = t >> 6;                  // owns j = qq*16..+15 within subtile
    const int iG = iG0 + i_loc;
    const bool ivalid = iG < NN;
    const float hdv = ivalid ? g_hd[b * NN + iG] : 0.f;
    float sacc = 0.f;

    { int jG = jbase + t; hs_s[t] = (jG < NN) ? g_hs[b * NN + jG] : 0.f; }

    const unsigned char* ab = (const unsigned char*)adj;
    const int* ai = (const int*)adj;
    const size_t bbase = (size_t)b * NN * NN;

    // smem addresses
    const uint32_t sPH = smem_to_u32(smPH), sPL = smem_to_u32(smPL);
    const uint32_t sHH = smem_to_u32(smHH), sHL = smem_to_u32(smHL);
    // ldmatrix A address (p): lane -> row wi*16+(lane&15), 16B half (lane>>4)
    const uint32_t aOff = (uint32_t)((wi * 16 + (lane & 15)) * PROW + (lane >> 4) * 16);
    // ldmatrix B address (h, trans): q=lane>>3, r=lane&7
    const int qb = lane >> 3, rb = lane & 7;
    const uint32_t bOff = (uint32_t)((((qb & 1) * 8 + rb) * PROW) + wdg * 64 + (qb >> 1) * 16);

    float D[4][4];
#pragma unroll
    for (int nb = 0; nb < 4; nb++)
#pragma unroll
        for (int e = 0; e < 4; e++) D[nb][e] = 0.f;

    for (int st = 0; st < 4; st++) {
        // ---- copy h subtile (hi/lo) into padded smem rows ----
        {
            int jl = t >> 2, seg = t & 3;
            int jG = jbase + st * 64 + jl;
            float4 z4 = make_float4(0.f, 0.f, 0.f, 0.f);
            const float4* srh = (const float4*)(g_hrh + ((size_t)b * 1024 + jG) * 64);
            const float4* srl = (const float4*)(g_hrl + ((size_t)b * 1024 + jG) * 64);
            bool ok = jG < NN;
            float4 h0 = ok ? __ldg(srh + seg) : z4;
            float4 h1 = ok ? __ldg(srh + seg + 4) : z4;
            float4 l0 = ok ? __ldg(srl + seg) : z4;
            float4 l1 = ok ? __ldg(srl + seg + 4) : z4;
            *(float4*)(smHH + jl * PROW + seg * 16) = h0;
            *(float4*)(smHH + jl * PROW + seg * 16 + 64) = h1;
            *(float4*)(smHL + jl * PROW + seg * 16) = l0;
            *(float4*)(smHL + jl * PROW + seg * 16 + 64) = l1;
        }
        // ---- p-phase: 16 j per thread, coalesced adj/dist ----
        {
            unsigned char av[16];
            float dv[16];
            int jG0 = jbase + st * 64 + qq * 16;
            if (ivalid && (jG0 + 16 <= NN)) {
                const float* dp = dist + (size_t)jG0 * NN + iG;
                if (!f4) {
                    const unsigned char* ap = ab + bbase + (size_t)jG0 * NN + iG;
#pragma unroll
                    for (int k = 0; k < 16; k++) {
                        av[k] = __ldg(ap + k * NN);
                        dv[k] = __ldg(dp + k * NN);
                    }
                } else {
                    const int* ap = ai + bbase + (size_t)jG0 * NN + iG;
#pragma unroll
                    for (int k = 0; k < 16; k++) {
                        av[k] = (unsigned char)(__ldg(ap + k * NN) != 0);
                        dv[k] = __ldg(dp + k * NN);
                    }
                }
            } else {
#pragma unroll
                for (int k = 0; k < 16; k++) {
                    int jG = jG0 + k;
                    bool ok = ivalid && (jG < NN);
                    av[k] = ok ? (f4 ? (unsigned char)(ai[bbase + (size_t)jG * NN + iG] != 0)
                                     : ab[bbase + (size_t)jG * NN + iG]) : 0;
                    dv[k] = ok ? __ldg(&dist[(size_t)jG * NN + iG]) : 0.f;
                }
            }
            uint32_t ph[8], pl[8];
#pragma unroll
            for (int m = 0; m < 8; m++) {
                float p0 = 0.f, p1 = 0.f;
                if (av[2 * m]) {
                    float ev = hdv + hs_s[st * 64 + qq * 16 + 2 * m] + wd * dv[2 * m];
                    ev = fmaxf(ev, 0.2f * ev);
                    p0 = __expf(ev);
                }
                if (av[2 * m + 1]) {
                    float ev = hdv + hs_s[st * 64 + qq * 16 + 2 * m + 1] + wd * dv[2 * m + 1];
                    ev = fmaxf(ev, 0.2f * ev);
                    p1 = __expf(ev);
                }
                sacc += p0 + p1;
                __nv_bfloat16 h0 = __float2bfloat16(p0);
                __nv_bfloat16 h1 = __float2bfloat16(p1);
                ph[m] = pkbf(h0, h1);
                pl[m] = pkbf(__float2bfloat16(p0 - __bfloat162float(h0)),
                             __float2bfloat16(p1 - __bfloat162float(h1)));
            }
            char* rp = smPH + i_loc * PROW + qq * 32;
            *(uint4*)rp = make_uint4(ph[0], ph[1], ph[2], ph[3]);
            *(uint4*)(rp + 16) = make_uint4(ph[4], ph[5], ph[6], ph[7]);
            char* rl = smPL + i_loc * PROW + qq * 32;
            *(uint4*)rl = make_uint4(pl[0], pl[1], pl[2], pl[3]);
            *(uint4*)(rl + 16) = make_uint4(pl[4], pl[5], pl[6], pl[7]);
        }
        __syncthreads();
        // ---- tensor MMA: 4 k-steps of 16 j ----
#pragma unroll
        for (int ks = 0; ks < 4; ks++) {
            uint32_t Ah[4], Al[4], Bh[8], Bl[8];
            ldsm_x4(Ah, sPH + aOff + ks * 32);
            ldsm_x4(Al, sPL + aOff + ks * 32);
            ldsm_x4_t(Bh,     sHH + bOff + ks * (16 * PROW));
            ldsm_x4_t(Bh + 4, sHH + bOff + ks * (16 * PROW) + 32);
            ldsm_x4_t(Bl,     sHL + bOff + ks * (16 * PROW));
            ldsm_x4_t(Bl + 4, sHL + bOff + ks * (16 * PROW) + 32);
#pragma unroll
            for (int nb = 0; nb < 4; nb++) {
                mma_bf16(D[nb], Ah, Bh[2 * nb], Bh[2 * nb + 1]);
                mma_bf16(D[nb], Ah, Bl[2 * nb], Bl[2 * nb + 1]);
                mma_bf16(D[nb], Al, Bh[2 * nb], Bh[2 * nb + 1]);
            }
        }
        __syncthreads();
    }

    // ---- s partials ----
    s_part[qq][i_loc] = sacc;
    __syncthreads();
    if (t < 64)
        g_spart[(size_t)pidx * 64 + t] = s_part[0][t] + s_part[1][t] + s_part[2][t] + s_part[3][t];
    // ---- D write ----
    float* pw = g_pacc + (size_t)pidx * 4096;
    int gg = lane >> 2, tg = lane & 3;
#pragma unroll
    for (int nb = 0; nb < 4; nb++) {
        int dc = wdg * 32 + nb * 8 + tg * 2;
        int il0 = wi * 16 + gg;
        pw[il0 * 64 + dc] = D[nb][0];
        pw[il0 * 64 + dc + 1] = D[nb][1];
        pw[(il0 + 8) * 64 + dc] = D[nb][2];
        pw[(il0 + 8) * 64 + dc + 1] = D[nb][3];
    }
}

// ---------------- GAT finalize: reduce chunks, divide, elu ----------------
__global__ __launch_bounds__(256) void gat_fin_kernel(float* __restrict__ outrep) {
    int it = blockIdx.x, b = blockIdx.y;
    int t = threadIdx.x;
    __shared__ float s_tot[64];
    if (t < 64) {
        float s = 0.f;
#pragma unroll
        for (int jcc = 0; jcc < NJC; jcc++)
            s += g_spart[(size_t)((b * NJC + jcc) * NIT + it) * 64 + t];
        s_tot[t] = s;
    }
    __syncthreads();
#pragma unroll
    for (int e = 0; e < 16; e++) {
        int idx = t + e * 256;
        int il = idx >> 6, d = idx & 63;
        int ig = it * 64 + il;
        if (ig >= NN) continue;
        float a = 0.f;
#pragma unroll
        for (int jcc = 0; jcc < NJC; jcc++)
            a += g_pacc[(size_t)((b * NJC + jcc) * NIT + it) * 4096 + idx];
        float s = s_tot[il];
        float inv = (s > 0.f) ? 1.f / s : 0.f;
        float v = a * inv;
        v = (v > 0.f) ? v : expm1f(v);
        outrep[((size_t)b * NN + ig) * DD + d] = v;
    }
}

// ---------------- x_p = sag @ Wp + bp (32 nodes/block) ----------------
__global__ __launch_bounds__(256) void xp_kernel(const int* __restrict__ time_idx,
                                                 const int* __restrict__ op_idx,
                                                 const float* __restrict__ vf,
                                                 const float* __restrict__ time_tab,
                                                 const float* __restrict__ cs_tab,
                                                 const float* __restrict__ tp_tab,
                                                 const float* __restrict__ Wp,
                                                 const float* __restrict__ bp,
                                                 float* __restrict__ xp) {
    __shared__ __align__(16) float sag[OBS][32];
    int t = threadIdx.x, w = t >> 5, lane = t & 31;
    size_t gn0 = (size_t)blockIdx.x * 32;
#pragma unroll
    for (int nl2 = 0; nl2 < 4; nl2++) {
        int node = w * 4 + nl2;
        size_t gn = gn0 + node;
        int n = (int)(gn % NN);
        int ti = time_idx[gn], op = op_idx[gn];
        for (int f = lane; f < OBS; f += 32) {
            float v;
            if (f < 4)       v = time_tab[ti * 4 + f];
            else if (f < 8)  v = cs_tab[n * 4 + (f - 4)];
            else if (f < 10) v = tp_tab[op * 2 + (f - 8)];
            else if (f < 19) v = vf[gn * 9 + (f - 10)];
            else if (f < 83) v = g_comp[gn * 64 + (f - 19)];
            else             v = g_coop[gn * 64 + (f - 83)];
            sag[f][node] = v;
        }
    }
    __syncthreads();
    int h = t;
    float bv = bp[h];
    unsigned long long acc2[16];
    unsigned long long bv2 = pk2(bv, bv);
#pragma unroll
    for (int k = 0; k < 16; k++) acc2[k] = bv2;
#pragma unroll 3
    for (int f = 0; f < OBS; f++) {
        float wv = Wp[f * HID + h];
        unsigned long long wv2 = pk2(wv, wv);
        const ulonglong2* sp = (const ulonglong2*)&sag[f][0];
#pragma unroll
        for (int k2 = 0; k2 < 8; k2++) {
            ulonglong2 s2 = sp[k2];
            acc2[2 * k2]     = ffma2(wv2, s2.x, acc2[2 * k2]);
            acc2[2 * k2 + 1] = ffma2(wv2, s2.y, acc2[2 * k2 + 1]);
        }
    }
#pragma unroll
    for (int k = 0; k < 16; k++) {
        float x0, x1;
        upk2(acc2[k], x0, x1);
        xp[(gn0 + 2 * k) * HID + h] = x0;
        xp[(gn0 + 2 * k + 1) * HID + h] = x1;
    }
}

// ---------------- scores = xp . vpd / vpf ----------------
__global__ void scores_kernel(const float* __restrict__ xp, const float* __restrict__ vpd,
                              const float* __restrict__ vpf) {
    int w = threadIdx.x >> 5, lane = threadIdx.x & 31;
    size_t gn = (size_t)blockIdx.x * 8 + w;
    const float* r = xp + gn * HID;
    float sd = 0.f, sf = 0.f;
#pragma unroll
    for (int k = 0; k < 8; k++) {
        int hh = lane + 32 * k;
        float v = r[hh];
        sd = fmaf(v, vpd[hh], sd);
        sf = fmaf(v, vpf[hh], sf);
    }
    for (int o = 16; o; o >>= 1) {
        sd += __shfl_xor_sync(0xffffffffu, sd, o);
        sf += __shfl_xor_sync(0xffffffffu, sf, o);
    }
    if (lane == 0) { g_scores[gn] = sf; g_scores[BN + gn] = sd; }
}

// ---------------- pooling: weights (sort + softmax) ----------------
__global__ __launch_bounds__(256) void pool_w_kernel(const void* __restrict__ dpcs) {
    int b = blockIdx.x, type = blockIdx.y;
    __shared__ float sc[1024];
    __shared__ float sraw[NN];
    __shared__ float red[256];
    int f4 = g_flag4;
    const float* srow = g_scores + (size_t)type * BN + (size_t)b * NN;

    float lm = -INFINITY;
    for (int n = threadIdx.x; n < NN; n += 256) lm = fmaxf(lm, srow[n]);
    red[threadIdx.x] = lm;
    __syncthreads();
    for (int o = 128; o; o >>= 1) {
        if (threadIdx.x < o) red[threadIdx.x] = fmaxf(red[threadIdx.x], red[threadIdx.x + o]);
        __syncthreads();
    }
    float gm = red[0];
    __syncthreads();

    for (int n = threadIdx.x; n < 1024; n += 256) {
        float v = -INFINITY;
        if (n < NN) {
            bool mk = bget(dpcs, (size_t)b * NN + n, f4);
            bool valid = type ? mk : !mk;
            float sv = valid ? (srow[n] - gm) : NEGV;
            sraw[n] = sv;
            v = sv;
        }
        sc[n] = v;
    }
    __syncthreads();

    for (int k = 2; k <= 1024; k <<= 1)
        for (int j = k >> 1; j > 0; j >>= 1) {
            for (int i = threadIdx.x; i < 1024; i += 256) {
                int ixj = i ^ j;
                if (ixj > i) {
                    float a = sc[i], c = sc[ixj];
                    bool dirAsc = (i & k) == 0;
                    bool sw = dirAsc ? (a < c) : (a > c);
                    if (sw) { sc[i] = c; sc[ixj] = a; }
                }
            }
            __syncthreads();
        }
    float th = sc[KSEL - 1];
    float mx = sc[0];

    float part = 0.f;
    for (int n = threadIdx.x; n < NN; n += 256) {
        float sv = sraw[n];
        float p = (sv >= th) ? __expf(sv - mx) : 0.f;
        sraw[n] = p;
        part += p;
    }
    __syncthreads();
    red[threadIdx.x] = part;
    __syncthreads();
    for (int o = 128; o; o >>= 1) {
        if (threadIdx.x < o) red[threadIdx.x] += red[threadIdx.x + o];
        __syncthreads();
    }
    float invS = 1.f / red[0];
    float* wrow = g_w + (size_t)type * BN + (size_t)b * NN;
    for (int n = threadIdx.x; n < NN; n += 256) wrow[n] = sraw[n] * invS;
}

// ---------------- pooling: partial weighted sum/max ----------------
__global__ __launch_bounds__(256) void pool_sum_kernel(const float* __restrict__ xp) {
    int b = blockIdx.x, type = blockIdx.y, q = blockIdx.z;
    int h = threadIdx.x;
    const float* wrow = g_w + (size_t)type * BN + (size_t)b * NN;
    const float* xpb = xp + (size_t)b * NN * HID + h;
    int n0 = q * 125, n1 = n0 + 125;
    float sum = 0.f, mxv = -INFINITY;
#pragma unroll 5
    for (int n = n0; n < n1; n++) {
        float xv = __ldg(&wrow[n]) * __ldg(&xpb[(size_t)n * HID]);
        sum += xv;
        mxv = fmaxf(mxv, xv);
    }
    float* pp = g_pp + ((((size_t)type * BB + b) * NQ + q) * 2) * HID;
    pp[h] = sum;
    pp[HID + h] = mxv;
}

// ---------------- pooling: combine ----------------
__global__ void pool_fin_kernel(float* __restrict__ out) {
    int b = blockIdx.x, type = blockIdx.y;
    int h = threadIdx.x;
    float sum = 0.f, mxv = -INFINITY;
#pragma unroll
    for (int q = 0; q < NQ; q++) {
        const float* pp = g_pp + ((((size_t)type * BB + b) * NQ + q) * 2) * HID;
        sum += pp[h];
        mxv = fmaxf(mxv, pp[HID + h]);
    }
    float* ob = out + (size_t)b * 1024 + type * 512;
    ob[h] = sum;
    ob[256 + h] = mxv;
}

// ---------------- launch ----------------
extern "C" void kernel_launch(void* const* d_in, const int* in_sizes, int n_in,
                              void* d_out, int out_size) {
    const int*   time_idx = (const int*)d_in[0];
    const int*   op_idx   = (const int*)d_in[1];
    const float* vf       = (const float*)d_in[2];
    const void*  dpcs     = d_in[3];
    const void*  adjc     = d_in[4];
    const void*  adjo     = d_in[5];
    const float* dist     = (const float*)d_in[6];
    const float* time_tab = (const float*)d_in[7];
    const float* tp_tab   = (const float*)d_in[8];
    const float* cs_tab   = (const float*)d_in[9];
    const float* Wc       = (const float*)d_in[10];
    const float* asrc_c   = (const float*)d_in[11];
    const float* adst_c   = (const float*)d_in[12];
    const float* wd_c     = (const float*)d_in[13];
    const float* Wco      = (const float*)d_in[14];
    const float* asrc_co  = (const float*)d_in[15];
    const float* adst_co  = (const float*)d_in[16];
    const float* wd_co    = (const float*)d_in[17];
    const float* Wp       = (const float*)d_in[18];
    const float* bp       = (const float*)d_in[19];
    const float* vpd      = (const float*)d_in[20];
    const float* vpf      = (const float*)d_in[21];
    float* out = (float*)d_out;

    float *pcomp, *pcoop, *pxp;
    cudaGetSymbolAddress((void**)&pcomp, g_comp);
    cudaGetSymbolAddress((void**)&pcoop, g_coop);
    cudaGetSymbolAddress((void**)&pxp,   g_xp);

    detect_kernel<<<1, 256>>>((const unsigned char*)adjc, 32000);

    h_kernel<<<BN / 4, 256>>>((const float*)nullptr, op_idx, vf, cs_tab, tp_tab,
                              Wc, asrc_c, adst_c);
    gat_kernel<<<dim3(NIT, NJC, BB), 256>>>(wd_c, adjc, dist);
    gat_fin_kernel<<<dim3(NIT, BB), 256>>>(pcomp);

    h_kernel<<<BN / 4, 256>>>(pcomp, op_idx, vf, cs_tab, tp_tab,
                              Wco, asrc_co, adst_co);
    gat_kernel<<<dim3(NIT, NJC, BB), 256>>>(wd_co, adjo, dist);
    gat_fin_kernel<<<dim3(NIT, BB), 256>>>(pcoop);

    xp_kernel<<<BN / 32, 256>>>(time_idx, op_idx, vf, time_tab, cs_tab, tp_tab, Wp, bp, pxp);
    scores_kernel<<<BN / 8, 256>>>(pxp, vpd, vpf);
    pool_w_kernel<<<dim3(BB, 2), 256>>>(dpcs);
    pool_sum_kernel<<<dim3(BB, 2, NQ), 256>>>(pxp);
    pool_fin_kernel<<<dim3(BB, 2), 256>>>(out);
}